// round 5
// baseline (speedup 1.0000x reference)
#include <cuda_runtime.h>

// BucketAdjustedHinge as fused per-(bucket,segment) piecewise-linear table:
// out = W[b][j]*x + C[b][j]. Table (64x21 float2, 10.7KB) built per block in
// smem. Exact-shape kernel: 1024 blocks x 256 thr x 4 unrolled iterations
// (n4 = 2^20), no bounds checks, prefetch-pipelined; 8 blocks/SM occupancy.

#define NB 64
#define KK 20
#define TS 21                   // KK + 1 (entry 0 = below all knots)
#define TPB 256
#define EB  1024                // exact-kernel blocks
#define ITERS 4                 // exact-kernel iterations per thread

__device__ __forceinline__ void build_table(
        float2* tab,
        const float* __restrict__ base_knots,
        const float* __restrict__ base_w,
        const float* __restrict__ base_b,
        const float* __restrict__ adj_knots,
        const float* __restrict__ adj_w,
        const float* __restrict__ adj_b,
        int tid) {
    if (tid < NB) {
        const int b = tid;
        float cb   = __ldg(base_b) + __ldg(adj_b + b);
        float runW = 0.0f;
        float runC = 0.0f;
        tab[b * TS] = make_float2(0.0f, cb);
#pragma unroll
        for (int j = 0; j < KK; ++j) {
            float bw = __ldg(base_w + j);
            float aw = __ldg(adj_w + b * KK + j);
            runW += bw + aw;
            runC = fmaf(bw, __ldg(base_knots + j), runC);
            runC = fmaf(aw, __ldg(adj_knots + b * KK + j), runC);
            tab[b * TS + j + 1] = make_float2(runW, cb - runC);
        }
    }
}

// index = b*TS + clamp(floor((x-k0)*ih)+1, 0, KK); eval = W*x + C
__device__ __forceinline__ float eval1(const float2* tab, float xf, int b,
                                       float ih, float c1) {
    int jp = __float2int_rd(fmaf(xf, ih, c1));   // floor(z)+1 folded into c1
    jp = min(max(jp, 0), KK);
    float2 t = tab[b * TS + jp];
    return fmaf(t.x, xf, t.y);
}

__global__ void __launch_bounds__(TPB, 8) bah_exact(
        const float4* __restrict__ x4,
        const int4*   __restrict__ b4,
        const float*  __restrict__ base_knots,
        const float*  __restrict__ base_w,
        const float*  __restrict__ base_b,
        const float*  __restrict__ adj_knots,
        const float*  __restrict__ adj_w,
        const float*  __restrict__ adj_b,
        float4*       __restrict__ out4) {
    __shared__ float2 tab[NB * TS];
    const int tid = threadIdx.x;
    build_table(tab, base_knots, base_w, base_b, adj_knots, adj_w, adj_b, tid);
    const float k0 = __ldg(base_knots);
    const float ih = (float)(KK - 1) / (__ldg(base_knots + KK - 1) - k0);
    const float c1 = 1.0f - k0 * ih;
    __syncthreads();

    const int stride = EB * TPB;            // 262144 float4s
    int idx = blockIdx.x * TPB + tid;

    float4 xc = x4[idx];
    int4   bc = b4[idx];
#pragma unroll
    for (int it = 0; it < ITERS; ++it) {
        float4 xn; int4 bn;
        if (it < ITERS - 1) {               // compile-time condition (unrolled)
            xn = x4[idx + stride];
            bn = b4[idx + stride];
        }
        float4 o;
        o.x = eval1(tab, xc.x, bc.x, ih, c1);
        o.y = eval1(tab, xc.y, bc.y, ih, c1);
        o.z = eval1(tab, xc.z, bc.z, ih, c1);
        o.w = eval1(tab, xc.w, bc.w, ih, c1);
        out4[idx] = o;
        xc = xn; bc = bn; idx += stride;
    }
}

// Generic fallback: persistent grid-stride (any n).
__global__ void __launch_bounds__(TPB, 8) bah_generic(
        const float*  __restrict__ x,
        const int*    __restrict__ bidx,
        const float*  __restrict__ base_knots,
        const float*  __restrict__ base_w,
        const float*  __restrict__ base_b,
        const float*  __restrict__ adj_knots,
        const float*  __restrict__ adj_w,
        const float*  __restrict__ adj_b,
        float*        __restrict__ out,
        int n) {
    __shared__ float2 tab[NB * TS];
    const int tid = threadIdx.x;
    build_table(tab, base_knots, base_w, base_b, adj_knots, adj_w, adj_b, tid);
    const float k0 = __ldg(base_knots);
    const float ih = (float)(KK - 1) / (__ldg(base_knots + KK - 1) - k0);
    const float c1 = 1.0f - k0 * ih;
    __syncthreads();

    const int n4     = n >> 2;
    const int stride = gridDim.x * TPB;
    const float4* __restrict__ x4   = (const float4*)x;
    const int4*   __restrict__ b4   = (const int4*)bidx;
    float4*       __restrict__ out4 = (float4*)out;

    for (int idx = blockIdx.x * TPB + tid; idx < n4; idx += stride) {
        float4 xv = x4[idx];
        int4   bv = b4[idx];
        float4 o;
        o.x = eval1(tab, xv.x, bv.x, ih, c1);
        o.y = eval1(tab, xv.y, bv.y, ih, c1);
        o.z = eval1(tab, xv.z, bv.z, ih, c1);
        o.w = eval1(tab, xv.w, bv.w, ih, c1);
        out4[idx] = o;
    }
    if (blockIdx.x == 0) {
        for (int i = (n4 << 2) + tid; i < n; i += TPB)
            out[i] = eval1(tab, x[i], bidx[i], ih, c1);
    }
}

extern "C" void kernel_launch(void* const* d_in, const int* in_sizes, int n_in,
                              void* d_out, int out_size) {
    const float* x          = (const float*)d_in[0];
    const int*   bidx       = (const int*)  d_in[1];
    const float* base_knots = (const float*)d_in[2];
    const float* base_w     = (const float*)d_in[3];
    const float* base_b     = (const float*)d_in[4];
    const float* adj_knots  = (const float*)d_in[5];
    const float* adj_w      = (const float*)d_in[6];
    const float* adj_b      = (const float*)d_in[7];

    int n = in_sizes[0];

    if (n == EB * TPB * ITERS * 4) {
        bah_exact<<<EB, TPB>>>((const float4*)x, (const int4*)bidx,
                               base_knots, base_w, base_b,
                               adj_knots, adj_w, adj_b, (float4*)d_out);
    } else {
        int n4 = n >> 2;
        int blocks = 148 * 8;
        int needed = (n4 + TPB - 1) / TPB;
        if (needed < blocks) blocks = needed;
        if (blocks < 1) blocks = 1;
        bah_generic<<<blocks, TPB>>>(x, bidx, base_knots, base_w, base_b,
                                     adj_knots, adj_w, adj_b, (float*)d_out, n);
    }
}

// round 6
// speedup vs baseline: 1.0025x; 1.0025x over previous
#include <cuda_runtime.h>

// BucketAdjustedHinge as fused per-(bucket,segment) piecewise-linear table:
// out = W[b][j]*x + C[b][j]. Table (64x21 float2, 10.7KB) built per block in
// smem. Exact-shape kernel: 1024 blocks x 256 thr x 4 iterations with a
// hand-scheduled depth-2 prefetch pipeline and streaming stores.

#define NB 64
#define KK 20
#define TS 21                   // KK + 1 (entry 0 = below all knots)
#define TPB 256
#define EB  1024                // exact-kernel blocks (n4 = 2^20 = EB*TPB*4)

__device__ __forceinline__ void build_table(
        float2* tab,
        const float* __restrict__ base_knots,
        const float* __restrict__ base_w,
        const float* __restrict__ base_b,
        const float* __restrict__ adj_knots,
        const float* __restrict__ adj_w,
        const float* __restrict__ adj_b,
        int tid) {
    if (tid < NB) {
        const int b = tid;
        float cb   = __ldg(base_b) + __ldg(adj_b + b);
        float runW = 0.0f;
        float runC = 0.0f;
        tab[b * TS] = make_float2(0.0f, cb);
#pragma unroll
        for (int j = 0; j < KK; ++j) {
            float bw = __ldg(base_w + j);
            float aw = __ldg(adj_w + b * KK + j);
            runW += bw + aw;
            runC = fmaf(bw, __ldg(base_knots + j), runC);
            runC = fmaf(aw, __ldg(adj_knots + b * KK + j), runC);
            tab[b * TS + j + 1] = make_float2(runW, cb - runC);
        }
    }
}

__device__ __forceinline__ float eval1(const float2* tab, float xf, int b,
                                       float ih, float c1) {
    int jp = __float2int_rd(fmaf(xf, ih, c1));   // floor((x-k0)*ih)+1 via c1
    jp = min(max(jp, 0), KK);
    float2 t = tab[b * TS + jp];
    return fmaf(t.x, xf, t.y);
}

__device__ __forceinline__ float4 eval4(const float2* tab, float4 xv, int4 bv,
                                        float ih, float c1) {
    float4 o;
    o.x = eval1(tab, xv.x, bv.x, ih, c1);
    o.y = eval1(tab, xv.y, bv.y, ih, c1);
    o.z = eval1(tab, xv.z, bv.z, ih, c1);
    o.w = eval1(tab, xv.w, bv.w, ih, c1);
    return o;
}

__global__ void __launch_bounds__(TPB) bah_exact(
        const float4* __restrict__ x4,
        const int4*   __restrict__ b4,
        const float*  __restrict__ base_knots,
        const float*  __restrict__ base_w,
        const float*  __restrict__ base_b,
        const float*  __restrict__ adj_knots,
        const float*  __restrict__ adj_w,
        const float*  __restrict__ adj_b,
        float4*       __restrict__ out4) {
    __shared__ float2 tab[NB * TS];
    const int tid = threadIdx.x;
    build_table(tab, base_knots, base_w, base_b, adj_knots, adj_w, adj_b, tid);
    const float k0 = __ldg(base_knots);
    const float ih = (float)(KK - 1) / (__ldg(base_knots + KK - 1) - k0);
    const float c1 = 1.0f - k0 * ih;
    __syncthreads();

    const int S = EB * TPB;                 // 262144 float4 stride
    const int i0 = blockIdx.x * TPB + tid;

    // depth-2 software pipeline over 4 iterations, stores interleaved
    float4 x0 = x4[i0];             int4 b0 = b4[i0];
    float4 x1 = x4[i0 + S];         int4 b1 = b4[i0 + S];

    float4 x2 = x4[i0 + 2 * S];     int4 b2 = b4[i0 + 2 * S];
    float4 o0 = eval4(tab, x0, b0, ih, c1);
    __stcs(&out4[i0], o0);

    float4 x3 = x4[i0 + 3 * S];     int4 b3 = b4[i0 + 3 * S];
    float4 o1 = eval4(tab, x1, b1, ih, c1);
    __stcs(&out4[i0 + S], o1);

    float4 o2 = eval4(tab, x2, b2, ih, c1);
    __stcs(&out4[i0 + 2 * S], o2);

    float4 o3 = eval4(tab, x3, b3, ih, c1);
    __stcs(&out4[i0 + 3 * S], o3);
}

// Generic fallback: persistent grid-stride (any n).
__global__ void __launch_bounds__(TPB) bah_generic(
        const float*  __restrict__ x,
        const int*    __restrict__ bidx,
        const float*  __restrict__ base_knots,
        const float*  __restrict__ base_w,
        const float*  __restrict__ base_b,
        const float*  __restrict__ adj_knots,
        const float*  __restrict__ adj_w,
        const float*  __restrict__ adj_b,
        float*        __restrict__ out,
        int n) {
    __shared__ float2 tab[NB * TS];
    const int tid = threadIdx.x;
    build_table(tab, base_knots, base_w, base_b, adj_knots, adj_w, adj_b, tid);
    const float k0 = __ldg(base_knots);
    const float ih = (float)(KK - 1) / (__ldg(base_knots + KK - 1) - k0);
    const float c1 = 1.0f - k0 * ih;
    __syncthreads();

    const int n4     = n >> 2;
    const int stride = gridDim.x * TPB;
    const float4* __restrict__ x4   = (const float4*)x;
    const int4*   __restrict__ b4   = (const int4*)bidx;
    float4*       __restrict__ out4 = (float4*)out;

    for (int idx = blockIdx.x * TPB + tid; idx < n4; idx += stride) {
        float4 xv = x4[idx];
        int4   bv = b4[idx];
        __stcs(&out4[idx], eval4(tab, xv, bv, ih, c1));
    }
    if (blockIdx.x == 0) {
        for (int i = (n4 << 2) + tid; i < n; i += TPB)
            out[i] = eval1(tab, x[i], bidx[i], ih, c1);
    }
}

extern "C" void kernel_launch(void* const* d_in, const int* in_sizes, int n_in,
                              void* d_out, int out_size) {
    const float* x          = (const float*)d_in[0];
    const int*   bidx       = (const int*)  d_in[1];
    const float* base_knots = (const float*)d_in[2];
    const float* base_w     = (const float*)d_in[3];
    const float* base_b     = (const float*)d_in[4];
    const float* adj_knots  = (const float*)d_in[5];
    const float* adj_w      = (const float*)d_in[6];
    const float* adj_b      = (const float*)d_in[7];

    int n = in_sizes[0];

    if (n == EB * TPB * 4 * 4) {
        bah_exact<<<EB, TPB>>>((const float4*)x, (const int4*)bidx,
                               base_knots, base_w, base_b,
                               adj_knots, adj_w, adj_b, (float4*)d_out);
    } else {
        int n4 = n >> 2;
        int blocks = 148 * 8;
        int needed = (n4 + TPB - 1) / TPB;
        if (needed < blocks) blocks = needed;
        if (blocks < 1) blocks = 1;
        bah_generic<<<blocks, TPB>>>(x, bidx, base_knots, base_w, base_b,
                                     adj_knots, adj_w, adj_b, (float*)d_out, n);
    }
}